// round 10
// baseline (speedup 1.0000x reference)
#include <cuda_runtime.h>
#include <cuda_bf16.h>
#include <math.h>

#define DD 1024
#define LMAX 288
#define LN_EPS 1e-5f
#define GELU_C 0.7978845608028654f

// ---------------- global scratch arena (floats) ----------------
constexpr size_t SZ_KV  = 16ull * LMAX * DD;            // 4,718,592
constexpr size_t OFF_K  = 0;
constexpr size_t OFF_V  = OFF_K + SZ_KV;
constexpr size_t OFF_H  = OFF_V + SZ_KV;                // prefill LN rows [4080][1024]
constexpr size_t OFF_E  = OFF_H + 4080ull * DD;         // current embedding [1024][16]
constexpr size_t OFF_HLN= OFF_E   + 16384;
constexpr size_t OFF_Q  = OFF_HLN + 16384;
constexpr size_t OFF_P  = OFF_Q   + 16384;              // probs [16][288]
constexpr size_t OFF_ATT= OFF_P   + 16ull*LMAX;
constexpr size_t OFF_X1 = OFF_ATT + 16384;
constexpr size_t OFF_H2 = OFF_X1  + 16384;
constexpr size_t OFF_FC = OFF_H2  + 16384;              // gelu(fc) [4096][16]
constexpr size_t OFF_X2 = OFF_FC  + 65536;
constexpr size_t OFF_XF = OFF_X2  + 16384;
constexpr size_t ARENA  = OFF_XF  + 16384;

__device__ float G[ARENA];
__device__ int   g_is64;

// ---------------- helpers ----------------
__device__ __forceinline__ float warp_sum(float v){
    #pragma unroll
    for (int o = 16; o; o >>= 1) v += __shfl_down_sync(0xffffffffu, v, o);
    return v;
}
__device__ __forceinline__ float warp_max(float v){
    #pragma unroll
    for (int o = 16; o; o >>= 1) v = fmaxf(v, __shfl_down_sync(0xffffffffu, v, o));
    return v;
}
__device__ __forceinline__ float blk_sum256(float v, float* red){
    int lane = threadIdx.x & 31, w = threadIdx.x >> 5;
    v = warp_sum(v);
    if (lane == 0) red[w] = v;
    __syncthreads();
    if (threadIdx.x < 32){
        float x = (threadIdx.x < 8) ? red[threadIdx.x] : 0.f;
        x = warp_sum(x);
        if (threadIdx.x == 0) red[0] = x;
    }
    __syncthreads();
    float r = red[0];
    __syncthreads();
    return r;
}
__device__ __forceinline__ float blk_max256(float v, float* red){
    int lane = threadIdx.x & 31, w = threadIdx.x >> 5;
    v = warp_max(v);
    if (lane == 0) red[w] = v;
    __syncthreads();
    if (threadIdx.x < 32){
        float x = (threadIdx.x < 8) ? red[threadIdx.x] : -3.4e38f;
        x = warp_max(x);
        if (threadIdx.x == 0) red[0] = x;
    }
    __syncthreads();
    float r = red[0];
    __syncthreads();
    return r;
}
__device__ __forceinline__ float tokf(const int* __restrict__ t, size_t i){
    return g_is64 ? (float)t[i << 1] : (float)t[i];
}
__device__ __forceinline__ float gelu_new_f(float x){
    float u = x + 0.044715f * x * x * x;
    return 0.5f * x * (1.0f + tanhf(GELU_C * u));
}

// ---------------- token dtype detector (int64 vs int32 storage) ----------------
__global__ void k_detect(const int* __restrict__ tok){
    __shared__ int cnt;
    if (threadIdx.x == 0) cnt = 0;
    __syncthreads();
    int c = 0;
    for (int i = threadIdx.x; i < 8192; i += 256)
        if (tok[2*i + 1] != 0) c++;
    atomicAdd(&cnt, c);
    __syncthreads();
    if (threadIdx.x == 0) g_is64 = (cnt == 0) ? 1 : 0;
}

// ---------------- prefill: LN1 of prefix rows 0..254 -> H (row-major) ----------------
__global__ void k_pre_ln(const int* __restrict__ tok,
                         const float* __restrict__ gam, const float* __restrict__ bet){
    __shared__ float red[8];
    int l = blockIdx.x, b = blockIdx.y, tid = threadIdx.x;
    size_t base = ((size_t)b * 256 + l) * DD;
    float x[4];
    #pragma unroll
    for (int r = 0; r < 4; r++) x[r] = tokf(tok, base + tid + 256*r);
    float mu = blk_sum256(x[0]+x[1]+x[2]+x[3], red) * (1.f / DD);
    float d0 = x[0]-mu, d1 = x[1]-mu, d2 = x[2]-mu, d3 = x[3]-mu;
    float var = blk_sum256(d0*d0 + d1*d1 + d2*d2 + d3*d3, red) * (1.f / DD);
    float rs = rsqrtf(var + LN_EPS);
    size_t o = OFF_H + ((size_t)b * 255 + l) * DD;
    G[o + tid        ] = d0*rs*gam[tid      ] + bet[tid      ];
    G[o + tid + 256  ] = d1*rs*gam[tid + 256] + bet[tid + 256];
    G[o + tid + 512  ] = d2*rs*gam[tid + 512] + bet[tid + 512];
    G[o + tid + 768  ] = d3*rs*gam[tid + 768] + bet[tid + 768];
}

// ---------------- prefill SGEMM: H[4080,1024] @ W_qkv[:,1024:3072] + b -> KV cache ----------------
__global__ void __launch_bounds__(256) k_pre_gemm(const float* __restrict__ Wq,
                                                  const float* __restrict__ bqkv){
    __shared__ float As[16][128];
    __shared__ float Bs[16][128];
    const int M = 16 * 255;
    int tid = threadIdx.x;
    int n0 = blockIdx.x * 128, m0 = blockIdx.y * 128;
    int tx = tid & 15, ty = tid >> 4;
    float acc[8][8];
    #pragma unroll
    for (int i = 0; i < 8; i++)
        #pragma unroll
        for (int j = 0; j < 8; j++) acc[i][j] = 0.f;

    int ar = tid >> 2;          // 0..63
    int ak = (tid & 3) * 4;     // 0,4,8,12
    int bk = tid >> 4;          // 0..15
    int bn = (tid & 15) * 4;    // 0..60

    for (int k0 = 0; k0 < 1024; k0 += 16){
        #pragma unroll
        for (int rr = 0; rr < 2; rr++){
            int m = m0 + ar + rr*64;
            float4 a = (m < M) ? *(const float4*)&G[OFF_H + (size_t)m*DD + k0 + ak]
                               : make_float4(0.f,0.f,0.f,0.f);
            As[ak+0][ar + rr*64] = a.x;
            As[ak+1][ar + rr*64] = a.y;
            As[ak+2][ar + rr*64] = a.z;
            As[ak+3][ar + rr*64] = a.w;
            float4 bv = *(const float4*)&Wq[(size_t)(k0 + bk)*3072 + 1024 + n0 + bn + rr*64];
            *(float4*)&Bs[bk][bn + rr*64] = bv;
        }
        __syncthreads();
        #pragma unroll
        for (int kk = 0; kk < 16; kk++){
            float ra[8], rb[8];
            *(float4*)&ra[0] = *(float4*)&As[kk][ty*8];
            *(float4*)&ra[4] = *(float4*)&As[kk][ty*8 + 4];
            *(float4*)&rb[0] = *(float4*)&Bs[kk][tx*8];
            *(float4*)&rb[4] = *(float4*)&Bs[kk][tx*8 + 4];
            #pragma unroll
            for (int i = 0; i < 8; i++)
                #pragma unroll
                for (int j = 0; j < 8; j++)
                    acc[i][j] = fmaf(ra[i], rb[j], acc[i][j]);
        }
        __syncthreads();
    }
    #pragma unroll
    for (int i = 0; i < 8; i++){
        int m = m0 + ty*8 + i;
        if (m >= M) continue;
        int bidx = m / 255, l = m % 255;
        size_t co = ((size_t)bidx * LMAX + l) * DD;
        #pragma unroll
        for (int j = 0; j < 8; j += 4){
            int n = n0 + tx*8 + j;
            float4 v;
            v.x = acc[i][j+0] + bqkv[1024 + n + 0];
            v.y = acc[i][j+1] + bqkv[1024 + n + 1];
            v.z = acc[i][j+2] + bqkv[1024 + n + 2];
            v.w = acc[i][j+3] + bqkv[1024 + n + 3];
            if (n < 1024) *(float4*)&G[OFF_K + co + n]        = v;
            else          *(float4*)&G[OFF_V + co + n - 1024] = v;
        }
    }
}

// ---------------- e0 = tokens[:,255,:] (feature-major [1024][16]) ----------------
__global__ void k_set_e0(const int* __restrict__ tok){
    int b = blockIdx.x, tid = threadIdx.x;
    size_t base = ((size_t)b * 256 + 255) * DD;
    #pragma unroll
    for (int r = 0; r < 4; r++){
        int d = tid + 256*r;
        G[OFF_E + (size_t)d*16 + b] = tokf(tok, base + d);
    }
}

// ---------------- layernorm on [1024][16] buffers ----------------
__global__ void k_ln(size_t in_off, size_t out_off,
                     const float* __restrict__ gam, const float* __restrict__ bet){
    __shared__ float red[8];
    int b = blockIdx.x, tid = threadIdx.x;
    float x[4];
    #pragma unroll
    for (int r = 0; r < 4; r++) x[r] = G[in_off + (size_t)(tid + 256*r)*16 + b];
    float mu = blk_sum256(x[0]+x[1]+x[2]+x[3], red) * (1.f / DD);
    float d0 = x[0]-mu, d1 = x[1]-mu, d2 = x[2]-mu, d3 = x[3]-mu;
    float var = blk_sum256(d0*d0 + d1*d1 + d2*d2 + d3*d3, red) * (1.f / DD);
    float rs = rsqrtf(var + LN_EPS);
    G[out_off + (size_t)(tid      )*16 + b] = d0*rs*gam[tid      ] + bet[tid      ];
    G[out_off + (size_t)(tid + 256)*16 + b] = d1*rs*gam[tid + 256] + bet[tid + 256];
    G[out_off + (size_t)(tid + 512)*16 + b] = d2*rs*gam[tid + 512] + bet[tid + 512];
    G[out_off + (size_t)(tid + 768)*16 + b] = d3*rs*gam[tid + 768] + bet[tid + 768];
}

// ---------------- batched-16 GEMV: Y[n][16] = X[K][16]^T @ W[K][N] (+epilogues) ----------------
// MODE 0: Y = r + bias
// MODE 1: qkv split -> Q buffer / K cache / V cache (pos)
// MODE 2: Y = R + r + bias (residual)
// MODE 3: Y = gelu(r + bias)
// MODE 4: score -> out logits + next embedding into Y(=E), no bias
template<int NC, int MODE, bool WT>
__global__ void __launch_bounds__(256) k_gemm(size_t xoff, const float* __restrict__ W,
                                              const float* __restrict__ bias,
                                              size_t yoff, size_t roff,
                                              int K, int N, int pos,
                                              float* __restrict__ out, int t){
    constexpr int TPC = 256 / NC;
    __shared__ float s[256 * 16];
    const float* X = &G[xoff];
    int c  = threadIdx.x & (NC - 1);
    int sl = threadIdx.x / NC;
    int n  = blockIdx.x * NC + c;
    int kper = K / TPC;
    int k0 = sl * kper;
    float acc[16];
    #pragma unroll
    for (int b = 0; b < 16; b++) acc[b] = 0.f;

    for (int k = k0; k < k0 + kper; k += 4){
        float w0, w1, w2, w3;
        if (WT){
            float4 w = *(const float4*)&W[(size_t)n*K + k];
            w0 = w.x; w1 = w.y; w2 = w.z; w3 = w.w;
        } else {
            w0 = W[(size_t)(k+0)*N + n];
            w1 = W[(size_t)(k+1)*N + n];
            w2 = W[(size_t)(k+2)*N + n];
            w3 = W[(size_t)(k+3)*N + n];
        }
        #pragma unroll
        for (int kk = 0; kk < 4; kk++){
            float wv = (kk==0) ? w0 : (kk==1) ? w1 : (kk==2) ? w2 : w3;
            const float4* xr = (const float4*)&X[(size_t)(k+kk)*16];
            float4 x0 = xr[0], x1 = xr[1], x2 = xr[2], x3 = xr[3];
            acc[ 0] = fmaf(wv, x0.x, acc[ 0]);
            acc[ 1] = fmaf(wv, x0.y, acc[ 1]);
            acc[ 2] = fmaf(wv, x0.z, acc[ 2]);
            acc[ 3] = fmaf(wv, x0.w, acc[ 3]);
            acc[ 4] = fmaf(wv, x1.x, acc[ 4]);
            acc[ 5] = fmaf(wv, x1.y, acc[ 5]);
            acc[ 6] = fmaf(wv, x1.z, acc[ 6]);
            acc[ 7] = fmaf(wv, x1.w, acc[ 7]);
            acc[ 8] = fmaf(wv, x2.x, acc[ 8]);
            acc[ 9] = fmaf(wv, x2.y, acc[ 9]);
            acc[10] = fmaf(wv, x2.z, acc[10]);
            acc[11] = fmaf(wv, x2.w, acc[11]);
            acc[12] = fmaf(wv, x3.x, acc[12]);
            acc[13] = fmaf(wv, x3.y, acc[13]);
            acc[14] = fmaf(wv, x3.z, acc[14]);
            acc[15] = fmaf(wv, x3.w, acc[15]);
        }
    }
    #pragma unroll
    for (int b = 0; b < 16; b += 4)
        *(float4*)&s[(size_t)(c*TPC + sl)*16 + b] = make_float4(acc[b], acc[b+1], acc[b+2], acc[b+3]);
    __syncthreads();

    for (int idx = threadIdx.x; idx < NC*16; idx += 256){
        int cc = idx >> 4, b = idx & 15;
        float r = 0.f;
        #pragma unroll 4
        for (int tc = 0; tc < TPC; tc++) r += s[(size_t)(cc*TPC + tc)*16 + b];
        int nn = blockIdx.x * NC + cc;
        if (MODE == 0){
            G[yoff + (size_t)nn*16 + b] = r + bias[nn];
        } else if (MODE == 1){
            float v = r + bias[nn];
            if (nn < 1024)      G[yoff + (size_t)nn*16 + b] = v;
            else if (nn < 2048) G[OFF_K + ((size_t)b*LMAX + pos)*DD + (nn - 1024)] = v;
            else                G[OFF_V + ((size_t)b*LMAX + pos)*DD + (nn - 2048)] = v;
        } else if (MODE == 2){
            G[yoff + (size_t)nn*16 + b] = G[roff + (size_t)nn*16 + b] + r + bias[nn];
        } else if (MODE == 3){
            G[yoff + (size_t)nn*16 + b] = gelu_new_f(r + bias[nn]);
        } else { // MODE 4
            out[(size_t)b*16384 + (size_t)t*512 + nn] = r;
            G[yoff + (size_t)(512 + nn)*16 + b] = (r > 0.f) ? 1.f : 0.f;
            G[yoff + (size_t)nn*16 + b] = 0.f;
        }
    }
}

// ---------------- attention: scores + softmax -> probs ----------------
__global__ void k_attn1(int t){
    __shared__ float sc[LMAX];
    __shared__ float qs[DD];
    __shared__ float red[8];
    int b = blockIdx.x, tid = threadIdx.x;
    int L = 256 + t;
    for (int d = tid; d < DD; d += 256) qs[d] = G[OFF_Q + (size_t)d*16 + b];
    __syncthreads();
    int warp = tid >> 5, lane = tid & 31;
    for (int l = warp; l < L; l += 8){
        const float* kc = &G[OFF_K + ((size_t)b*LMAX + l)*DD];
        float a = 0.f;
        #pragma unroll
        for (int i = 0; i < 8; i++){
            int d = lane*4 + i*128;
            float4 kv = *(const float4*)&kc[d];
            float4 qv = *(const float4*)&qs[d];
            a = fmaf(kv.x, qv.x, a);
            a = fmaf(kv.y, qv.y, a);
            a = fmaf(kv.z, qv.z, a);
            a = fmaf(kv.w, qv.w, a);
        }
        a = warp_sum(a);
        if (lane == 0) sc[l] = a * 0.03125f;   // 1/sqrt(1024)
    }
    __syncthreads();
    float m = -3.4e38f;
    for (int l = tid; l < L; l += 256) m = fmaxf(m, sc[l]);
    m = blk_max256(m, red);
    float e = 0.f;
    for (int l = tid; l < L; l += 256){
        float ev = expf(sc[l] - m);
        sc[l] = ev;
        e += ev;
    }
    float Z = blk_sum256(e, red);
    float iz = 1.f / Z;
    for (int l = tid; l < L; l += 256)
        G[OFF_P + (size_t)b*LMAX + l] = sc[l] * iz;
}

// ---------------- attention: att = probs @ V ----------------
__global__ void k_attn2(int t){
    int b = blockIdx.y;
    int d = blockIdx.x * 128 + threadIdx.x;
    int L = 256 + t;
    const float* p  = &G[OFF_P + (size_t)b*LMAX];
    const float* vc = &G[OFF_V + (size_t)b*LMAX*DD + d];
    float a0 = 0.f, a1 = 0.f, a2 = 0.f, a3 = 0.f;
    int l = 0;
    for (; l + 4 <= L; l += 4){
        a0 = fmaf(p[l+0], vc[(size_t)(l+0)*DD], a0);
        a1 = fmaf(p[l+1], vc[(size_t)(l+1)*DD], a1);
        a2 = fmaf(p[l+2], vc[(size_t)(l+2)*DD], a2);
        a3 = fmaf(p[l+3], vc[(size_t)(l+3)*DD], a3);
    }
    for (; l < L; l++) a0 = fmaf(p[l], vc[(size_t)l*DD], a0);
    G[OFF_ATT + (size_t)d*16 + b] = (a0 + a1) + (a2 + a3);
}

// ---------------- host ----------------
extern "C" void kernel_launch(void* const* d_in, const int* in_sizes, int n_in,
                              void* d_out, int out_size){
    const int*   tok     = (const int*)  d_in[0];
    const float* W_qkv   = (const float*)d_in[1];
    const float* b_qkv   = (const float*)d_in[2];
    const float* W_aproj = (const float*)d_in[3];
    const float* b_aproj = (const float*)d_in[4];
    const float* g_ln1   = (const float*)d_in[5];
    const float* b_ln1   = (const float*)d_in[6];
    const float* g_ln2   = (const float*)d_in[7];
    const float* b_ln2   = (const float*)d_in[8];
    const float* W_fc    = (const float*)d_in[9];
    const float* b_fc    = (const float*)d_in[10];
    const float* W_mproj = (const float*)d_in[11];
    const float* b_mproj = (const float*)d_in[12];
    const float* g_lnf   = (const float*)d_in[13];
    const float* b_lnf   = (const float*)d_in[14];
    const float* W_score = (const float*)d_in[15];
    float* out = (float*)d_out;

    k_detect<<<1, 256>>>(tok);
    k_pre_ln<<<dim3(255, 16), 256>>>(tok, g_ln1, b_ln1);
    k_pre_gemm<<<dim3(16, 32), 256>>>(W_qkv, b_qkv);
    k_set_e0<<<16, 256>>>(tok);

    for (int t = 0; t < 32; t++){
        int pos = 255 + t;
        // LN1(E) -> HLN
        k_ln<<<16, 256>>>(OFF_E, OFF_HLN, g_ln1, b_ln1);
        // qkv: HLN @ W_qkv -> Q buffer + KV cache at pos
        k_gemm<32, 1, false><<<3072/32, 256>>>(OFF_HLN, W_qkv, b_qkv, OFF_Q, 0,
                                               1024, 3072, pos, out, t);
        // attention
        k_attn1<<<16, 256>>>(t);
        k_attn2<<<dim3(8, 16), 128>>>(t);
        // x1 = E + att @ W_aproj + b
        k_gemm<8, 2, false><<<1024/8, 256>>>(OFF_ATT, W_aproj, b_aproj, OFF_X1, OFF_E,
                                             1024, 1024, pos, out, t);
        // LN2(x1) -> H2
        k_ln<<<16, 256>>>(OFF_X1, OFF_H2, g_ln2, b_ln2);
        // fc = gelu(H2 @ W_fc + b)
        k_gemm<32, 3, false><<<4096/32, 256>>>(OFF_H2, W_fc, b_fc, OFF_FC, 0,
                                               1024, 4096, pos, out, t);
        // x2 = x1 + fc @ W_mproj + b
        k_gemm<8, 2, false><<<1024/8, 256>>>(OFF_FC, W_mproj, b_mproj, OFF_X2, OFF_X1,
                                             4096, 1024, pos, out, t);
        // LNf(x2) -> XF
        k_ln<<<16, 256>>>(OFF_X2, OFF_XF, g_lnf, b_lnf);
        // logits = XF @ W_score^T -> out[:,t,:] ; next embedding -> E
        k_gemm<4, 4, true><<<512/4, 256>>>(OFF_XF, W_score, b_qkv /*unused*/, OFF_E, 0,
                                           1024, 512, pos, out, t);
    }
}

// round 11
// speedup vs baseline: 1.0310x; 1.0310x over previous
#include <cuda_runtime.h>
#include <cuda_bf16.h>
#include <math.h>

#define DD 1024
#define LMAX 288
#define LN_EPS 1e-5f
#define GELU_C 0.7978845608028654f

// ---------------- global scratch arena (floats) ----------------
constexpr size_t SZ_KV  = 16ull * LMAX * DD;            // 4,718,592
constexpr size_t OFF_K  = 0;
constexpr size_t OFF_V  = OFF_K + SZ_KV;
constexpr size_t OFF_H  = OFF_V + SZ_KV;                // prefill LN rows [4080][1024]
constexpr size_t OFF_E  = OFF_H + 4080ull * DD;         // current embedding [1024][16]
constexpr size_t OFF_HLN= OFF_E   + 16384;
constexpr size_t OFF_Q  = OFF_HLN + 16384;
constexpr size_t OFF_P  = OFF_Q   + 16384;              // probs [16][288]
constexpr size_t OFF_ATT= OFF_P   + 16ull*LMAX;
constexpr size_t OFF_X1 = OFF_ATT + 16384;
constexpr size_t OFF_H2 = OFF_X1  + 16384;
constexpr size_t OFF_FC = OFF_H2  + 16384;              // gelu(fc) [4096][16]
constexpr size_t OFF_X2 = OFF_FC  + 65536;
constexpr size_t OFF_XF = OFF_X2  + 16384;
constexpr size_t ARENA  = OFF_XF  + 16384;

__device__ float G[ARENA];
__device__ int   g_is64;

// ---------------- helpers ----------------
__device__ __forceinline__ float warp_sum(float v){
    #pragma unroll
    for (int o = 16; o; o >>= 1) v += __shfl_down_sync(0xffffffffu, v, o);
    return v;
}
__device__ __forceinline__ float warp_max(float v){
    #pragma unroll
    for (int o = 16; o; o >>= 1) v = fmaxf(v, __shfl_down_sync(0xffffffffu, v, o));
    return v;
}
__device__ __forceinline__ float blk_sum256(float v, float* red){
    int lane = threadIdx.x & 31, w = threadIdx.x >> 5;
    v = warp_sum(v);
    if (lane == 0) red[w] = v;
    __syncthreads();
    if (threadIdx.x < 32){
        float x = (threadIdx.x < 8) ? red[threadIdx.x] : 0.f;
        x = warp_sum(x);
        if (threadIdx.x == 0) red[0] = x;
    }
    __syncthreads();
    float r = red[0];
    __syncthreads();
    return r;
}
__device__ __forceinline__ float blk_max256(float v, float* red){
    int lane = threadIdx.x & 31, w = threadIdx.x >> 5;
    v = warp_max(v);
    if (lane == 0) red[w] = v;
    __syncthreads();
    if (threadIdx.x < 32){
        float x = (threadIdx.x < 8) ? red[threadIdx.x] : -3.4e38f;
        x = warp_max(x);
        if (threadIdx.x == 0) red[0] = x;
    }
    __syncthreads();
    float r = red[0];
    __syncthreads();
    return r;
}
__device__ __forceinline__ float tokf(const int* __restrict__ t, size_t i){
    return g_is64 ? (float)t[i << 1] : (float)t[i];
}
__device__ __forceinline__ float gelu_new_f(float x){
    float u = x + 0.044715f * x * x * x;
    return 0.5f * x * (1.0f + tanhf(GELU_C * u));
}

// ---------------- token dtype detector (int64 vs int32 storage) ----------------
__global__ void k_detect(const int* __restrict__ tok){
    __shared__ int cnt;
    if (threadIdx.x == 0) cnt = 0;
    __syncthreads();
    int c = 0;
    for (int i = threadIdx.x; i < 8192; i += 256)
        if (tok[2*i + 1] != 0) c++;
    atomicAdd(&cnt, c);
    __syncthreads();
    if (threadIdx.x == 0) g_is64 = (cnt == 0) ? 1 : 0;
}

// ---------------- prefill: LN1 of prefix rows 0..254 -> H (row-major) ----------------
__global__ void k_pre_ln(const int* __restrict__ tok,
                         const float* __restrict__ gam, const float* __restrict__ bet){
    __shared__ float red[8];
    int l = blockIdx.x, b = blockIdx.y, tid = threadIdx.x;
    size_t base = ((size_t)b * 256 + l) * DD;
    float x[4];
    #pragma unroll
    for (int r = 0; r < 4; r++) x[r] = tokf(tok, base + tid + 256*r);
    float mu = blk_sum256(x[0]+x[1]+x[2]+x[3], red) * (1.f / DD);
    float d0 = x[0]-mu, d1 = x[1]-mu, d2 = x[2]-mu, d3 = x[3]-mu;
    float var = blk_sum256(d0*d0 + d1*d1 + d2*d2 + d3*d3, red) * (1.f / DD);
    float rs = rsqrtf(var + LN_EPS);
    size_t o = OFF_H + ((size_t)b * 255 + l) * DD;
    G[o + tid        ] = d0*rs*gam[tid      ] + bet[tid      ];
    G[o + tid + 256  ] = d1*rs*gam[tid + 256] + bet[tid + 256];
    G[o + tid + 512  ] = d2*rs*gam[tid + 512] + bet[tid + 512];
    G[o + tid + 768  ] = d3*rs*gam[tid + 768] + bet[tid + 768];
}

// ---------------- prefill SGEMM: H[4080,1024] @ W_qkv[:,1024:3072] + b -> KV cache ----------------
__global__ void __launch_bounds__(256) k_pre_gemm(const float* __restrict__ Wq,
                                                  const float* __restrict__ bqkv){
    __shared__ float As[16][128];
    __shared__ float Bs[16][128];
    const int M = 16 * 255;
    int tid = threadIdx.x;
    int n0 = blockIdx.x * 128, m0 = blockIdx.y * 128;
    int tx = tid & 15, ty = tid >> 4;
    float acc[8][8];
    #pragma unroll
    for (int i = 0; i < 8; i++)
        #pragma unroll
        for (int j = 0; j < 8; j++) acc[i][j] = 0.f;

    int ar = tid >> 2;          // 0..63
    int ak = (tid & 3) * 4;     // 0,4,8,12
    int bk = tid >> 4;          // 0..15
    int bn = (tid & 15) * 4;    // 0..60

    for (int k0 = 0; k0 < 1024; k0 += 16){
        #pragma unroll
        for (int rr = 0; rr < 2; rr++){
            int m = m0 + ar + rr*64;
            float4 a = (m < M) ? *(const float4*)&G[OFF_H + (size_t)m*DD + k0 + ak]
                               : make_float4(0.f,0.f,0.f,0.f);
            As[ak+0][ar + rr*64] = a.x;
            As[ak+1][ar + rr*64] = a.y;
            As[ak+2][ar + rr*64] = a.z;
            As[ak+3][ar + rr*64] = a.w;
            float4 bv = *(const float4*)&Wq[(size_t)(k0 + bk)*3072 + 1024 + n0 + bn + rr*64];
            *(float4*)&Bs[bk][bn + rr*64] = bv;
        }
        __syncthreads();
        #pragma unroll
        for (int kk = 0; kk < 16; kk++){
            float ra[8], rb[8];
            *(float4*)&ra[0] = *(float4*)&As[kk][ty*8];
            *(float4*)&ra[4] = *(float4*)&As[kk][ty*8 + 4];
            *(float4*)&rb[0] = *(float4*)&Bs[kk][tx*8];
            *(float4*)&rb[4] = *(float4*)&Bs[kk][tx*8 + 4];
            #pragma unroll
            for (int i = 0; i < 8; i++)
                #pragma unroll
                for (int j = 0; j < 8; j++)
                    acc[i][j] = fmaf(ra[i], rb[j], acc[i][j]);
        }
        __syncthreads();
    }
    #pragma unroll
    for (int i = 0; i < 8; i++){
        int m = m0 + ty*8 + i;
        if (m >= M) continue;
        int bidx = m / 255, l = m % 255;
        size_t co = ((size_t)bidx * LMAX + l) * DD;
        #pragma unroll
        for (int j = 0; j < 8; j += 4){
            int n = n0 + tx*8 + j;
            float4 v;
            v.x = acc[i][j+0] + bqkv[1024 + n + 0];
            v.y = acc[i][j+1] + bqkv[1024 + n + 1];
            v.z = acc[i][j+2] + bqkv[1024 + n + 2];
            v.w = acc[i][j+3] + bqkv[1024 + n + 3];
            if (n < 1024) *(float4*)&G[OFF_K + co + n]        = v;
            else          *(float4*)&G[OFF_V + co + n - 1024] = v;
        }
    }
}

// ---------------- e0 = tokens[:,255,:] (feature-major [1024][16]) ----------------
__global__ void k_set_e0(const int* __restrict__ tok){
    int b = blockIdx.x, tid = threadIdx.x;
    size_t base = ((size_t)b * 256 + 255) * DD;
    #pragma unroll
    for (int r = 0; r < 4; r++){
        int d = tid + 256*r;
        G[OFF_E + (size_t)d*16 + b] = tokf(tok, base + d);
    }
}

// ---------------- layernorm on [1024][16] buffers ----------------
__global__ void k_ln(size_t in_off, size_t out_off,
                     const float* __restrict__ gam, const float* __restrict__ bet){
    __shared__ float red[8];
    int b = blockIdx.x, tid = threadIdx.x;
    float x[4];
    #pragma unroll
    for (int r = 0; r < 4; r++) x[r] = G[in_off + (size_t)(tid + 256*r)*16 + b];
    float mu = blk_sum256(x[0]+x[1]+x[2]+x[3], red) * (1.f / DD);
    float d0 = x[0]-mu, d1 = x[1]-mu, d2 = x[2]-mu, d3 = x[3]-mu;
    float var = blk_sum256(d0*d0 + d1*d1 + d2*d2 + d3*d3, red) * (1.f / DD);
    float rs = rsqrtf(var + LN_EPS);
    G[out_off + (size_t)(tid      )*16 + b] = d0*rs*gam[tid      ] + bet[tid      ];
    G[out_off + (size_t)(tid + 256)*16 + b] = d1*rs*gam[tid + 256] + bet[tid + 256];
    G[out_off + (size_t)(tid + 512)*16 + b] = d2*rs*gam[tid + 512] + bet[tid + 512];
    G[out_off + (size_t)(tid + 768)*16 + b] = d3*rs*gam[tid + 768] + bet[tid + 768];
}

// ---------------- batched-16 GEMV: Y[n][16] = X[K][16]^T @ W[K][N] (+epilogues) ----------------
// MODE 0: Y = r + bias
// MODE 1: qkv split -> Q buffer / K cache / V cache (pos)
// MODE 2: Y = R + r + bias (residual)
// MODE 3: Y = gelu(r + bias)
// MODE 4: score -> out logits + next embedding into Y(=E), no bias
template<int NC, int MODE, bool WT>
__global__ void __launch_bounds__(256) k_gemm(size_t xoff, const float* __restrict__ W,
                                              const float* __restrict__ bias,
                                              size_t yoff, size_t roff,
                                              int K, int N, int pos,
                                              float* __restrict__ out, int t){
    constexpr int TPC = 256 / NC;
    __shared__ float s[256 * 16];
    const float* X = &G[xoff];
    int c  = threadIdx.x & (NC - 1);
    int sl = threadIdx.x / NC;
    int n  = blockIdx.x * NC + c;
    int kper = K / TPC;
    int k0 = sl * kper;
    float acc[16];
    #pragma unroll
    for (int b = 0; b < 16; b++) acc[b] = 0.f;

    for (int k = k0; k < k0 + kper; k += 4){
        float w0, w1, w2, w3;
        if (WT){
            float4 w = *(const float4*)&W[(size_t)n*K + k];
            w0 = w.x; w1 = w.y; w2 = w.z; w3 = w.w;
        } else {
            w0 = W[(size_t)(k+0)*N + n];
            w1 = W[(size_t)(k+1)*N + n];
            w2 = W[(size_t)(k+2)*N + n];
            w3 = W[(size_t)(k+3)*N + n];
        }
        #pragma unroll
        for (int kk = 0; kk < 4; kk++){
            float wv = (kk==0) ? w0 : (kk==1) ? w1 : (kk==2) ? w2 : w3;
            const float4* xr = (const float4*)&X[(size_t)(k+kk)*16];
            float4 x0 = xr[0], x1 = xr[1], x2 = xr[2], x3 = xr[3];
            acc[ 0] = fmaf(wv, x0.x, acc[ 0]);
            acc[ 1] = fmaf(wv, x0.y, acc[ 1]);
            acc[ 2] = fmaf(wv, x0.z, acc[ 2]);
            acc[ 3] = fmaf(wv, x0.w, acc[ 3]);
            acc[ 4] = fmaf(wv, x1.x, acc[ 4]);
            acc[ 5] = fmaf(wv, x1.y, acc[ 5]);
            acc[ 6] = fmaf(wv, x1.z, acc[ 6]);
            acc[ 7] = fmaf(wv, x1.w, acc[ 7]);
            acc[ 8] = fmaf(wv, x2.x, acc[ 8]);
            acc[ 9] = fmaf(wv, x2.y, acc[ 9]);
            acc[10] = fmaf(wv, x2.z, acc[10]);
            acc[11] = fmaf(wv, x2.w, acc[11]);
            acc[12] = fmaf(wv, x3.x, acc[12]);
            acc[13] = fmaf(wv, x3.y, acc[13]);
            acc[14] = fmaf(wv, x3.z, acc[14]);
            acc[15] = fmaf(wv, x3.w, acc[15]);
        }
    }
    #pragma unroll
    for (int b = 0; b < 16; b += 4)
        *(float4*)&s[(size_t)(c*TPC + sl)*16 + b] = make_float4(acc[b], acc[b+1], acc[b+2], acc[b+3]);
    __syncthreads();

    for (int idx = threadIdx.x; idx < NC*16; idx += 256){
        int cc = idx >> 4, b = idx & 15;
        float r = 0.f;
        #pragma unroll 4
        for (int tc = 0; tc < TPC; tc++) r += s[(size_t)(cc*TPC + tc)*16 + b];
        int nn = blockIdx.x * NC + cc;
        if (MODE == 0){
            G[yoff + (size_t)nn*16 + b] = r + bias[nn];
        } else if (MODE == 1){
            float v = r + bias[nn];
            if (nn < 1024)      G[yoff + (size_t)nn*16 + b] = v;
            else if (nn < 2048) G[OFF_K + ((size_t)b*LMAX + pos)*DD + (nn - 1024)] = v;
            else                G[OFF_V + ((size_t)b*LMAX + pos)*DD + (nn - 2048)] = v;
        } else if (MODE == 2){
            G[yoff + (size_t)nn*16 + b] = G[roff + (size_t)nn*16 + b] + r + bias[nn];
        } else if (MODE == 3){
            G[yoff + (size_t)nn*16 + b] = gelu_new_f(r + bias[nn]);
        } else { // MODE 4
            out[(size_t)b*16384 + (size_t)t*512 + nn] = r;
            G[yoff + (size_t)(512 + nn)*16 + b] = (r > 0.f) ? 1.f : 0.f;
            G[yoff + (size_t)nn*16 + b] = 0.f;
        }
    }
}

// ---------------- attention: scores + softmax -> probs ----------------
__global__ void k_attn1(int t){
    __shared__ float sc[LMAX];
    __shared__ float qs[DD];
    __shared__ float red[8];
    int b = blockIdx.x, tid = threadIdx.x;
    int L = 256 + t;
    for (int d = tid; d < DD; d += 256) qs[d] = G[OFF_Q + (size_t)d*16 + b];
    __syncthreads();
    int warp = tid >> 5, lane = tid & 31;
    for (int l = warp; l < L; l += 8){
        const float* kc = &G[OFF_K + ((size_t)b*LMAX + l)*DD];
        float a = 0.f;
        #pragma unroll
        for (int i = 0; i < 8; i++){
            int d = lane*4 + i*128;
            float4 kv = *(const float4*)&kc[d];
            float4 qv = *(const float4*)&qs[d];
            a = fmaf(kv.x, qv.x, a);
            a = fmaf(kv.y, qv.y, a);
            a = fmaf(kv.z, qv.z, a);
            a = fmaf(kv.w, qv.w, a);
        }
        a = warp_sum(a);
        if (lane == 0) sc[l] = a * 0.03125f;   // 1/sqrt(1024)
    }
    __syncthreads();
    float m = -3.4e38f;
    for (int l = tid; l < L; l += 256) m = fmaxf(m, sc[l]);
    m = blk_max256(m, red);
    float e = 0.f;
    for (int l = tid; l < L; l += 256){
        float ev = expf(sc[l] - m);
        sc[l] = ev;
        e += ev;
    }
    float Z = blk_sum256(e, red);
    float iz = 1.f / Z;
    for (int l = tid; l < L; l += 256)
        G[OFF_P + (size_t)b*LMAX + l] = sc[l] * iz;
}

// ---------------- attention: att = probs @ V ----------------
__global__ void k_attn2(int t){
    int b = blockIdx.y;
    int d = blockIdx.x * 128 + threadIdx.x;
    int L = 256 + t;
    const float* p  = &G[OFF_P + (size_t)b*LMAX];
    const float* vc = &G[OFF_V + (size_t)b*LMAX*DD + d];
    float a0 = 0.f, a1 = 0.f, a2 = 0.f, a3 = 0.f;
    int l = 0;
    for (; l + 4 <= L; l += 4){
        a0 = fmaf(p[l+0], vc[(size_t)(l+0)*DD], a0);
        a1 = fmaf(p[l+1], vc[(size_t)(l+1)*DD], a1);
        a2 = fmaf(p[l+2], vc[(size_t)(l+2)*DD], a2);
        a3 = fmaf(p[l+3], vc[(size_t)(l+3)*DD], a3);
    }
    for (; l < L; l++) a0 = fmaf(p[l], vc[(size_t)l*DD], a0);
    G[OFF_ATT + (size_t)d*16 + b] = (a0 + a1) + (a2 + a3);
}

// ---------------- host ----------------
extern "C" void kernel_launch(void* const* d_in, const int* in_sizes, int n_in,
                              void* d_out, int out_size){
    const int*   tok     = (const int*)  d_in[0];
    const float* W_qkv   = (const float*)d_in[1];
    const float* b_qkv   = (const float*)d_in[2];
    const float* W_aproj = (const float*)d_in[3];
    const float* b_aproj = (const float*)d_in[4];
    const float* g_ln1   = (const float*)d_in[5];
    const float* b_ln1   = (const float*)d_in[6];
    const float* g_ln2   = (const float*)d_in[7];
    const float* b_ln2   = (const float*)d_in[8];
    const float* W_fc    = (const float*)d_in[9];
    const float* b_fc    = (const float*)d_in[10];
    const float* W_mproj = (const float*)d_in[11];
    const float* b_mproj = (const float*)d_in[12];
    const float* g_lnf   = (const float*)d_in[13];
    const float* b_lnf   = (const float*)d_in[14];
    const float* W_score = (const float*)d_in[15];
    float* out = (float*)d_out;

    k_detect<<<1, 256>>>(tok);
    k_pre_ln<<<dim3(255, 16), 256>>>(tok, g_ln1, b_ln1);
    k_pre_gemm<<<dim3(16, 32), 256>>>(W_qkv, b_qkv);
    k_set_e0<<<16, 256>>>(tok);

    for (int t = 0; t < 32; t++){
        int pos = 255 + t;
        // LN1(E) -> HLN
        k_ln<<<16, 256>>>(OFF_E, OFF_HLN, g_ln1, b_ln1);
        // qkv: HLN @ W_qkv -> Q buffer + KV cache at pos
        k_gemm<32, 1, false><<<3072/32, 256>>>(OFF_HLN, W_qkv, b_qkv, OFF_Q, 0,
                                               1024, 3072, pos, out, t);
        // attention
        k_attn1<<<16, 256>>>(t);
        k_attn2<<<dim3(8, 16), 128>>>(t);
        // x1 = E + att @ W_aproj + b
        k_gemm<8, 2, false><<<1024/8, 256>>>(OFF_ATT, W_aproj, b_aproj, OFF_X1, OFF_E,
                                             1024, 1024, pos, out, t);
        // LN2(x1) -> H2
        k_ln<<<16, 256>>>(OFF_X1, OFF_H2, g_ln2, b_ln2);
        // fc = gelu(H2 @ W_fc + b)
        k_gemm<32, 3, false><<<4096/32, 256>>>(OFF_H2, W_fc, b_fc, OFF_FC, 0,
                                               1024, 4096, pos, out, t);
        // x2 = x1 + fc @ W_mproj + b
        k_gemm<8, 2, false><<<1024/8, 256>>>(OFF_FC, W_mproj, b_mproj, OFF_X2, OFF_X1,
                                             4096, 1024, pos, out, t);
        // LNf(x2) -> XF
        k_ln<<<16, 256>>>(OFF_X2, OFF_XF, g_lnf, b_lnf);
        // logits = XF @ W_score^T -> out[:,t,:] ; next embedding -> E
        k_gemm<4, 4, true><<<512/4, 256>>>(OFF_XF, W_score, b_qkv /*unused*/, OFF_E, 0,
                                           1024, 512, pos, out, t);
    }
}

// round 12
// speedup vs baseline: 2.3642x; 2.2930x over previous
#include <cuda_runtime.h>
#include <math.h>

#define DD 1024
#define LMAX 288
#define NBLK 148
#define LN_EPS 1e-5f
#define GELU_C 0.7978845608028654f

// ---------------- arena ----------------
constexpr size_t OFF_K  = 0;
constexpr size_t OFF_V  = OFF_K + 16ull*LMAX*DD;
constexpr size_t OFF_H  = OFF_V + 16ull*LMAX*DD;
constexpr size_t OFF_E  = OFF_H + 4080ull*DD;
constexpr size_t OFF_Q  = OFF_E   + 16384;
constexpr size_t OFF_ATT= OFF_Q   + 16384;
constexpr size_t OFF_X1 = OFF_ATT + 16384;
constexpr size_t OFF_FC = OFF_X1  + 16384;
constexpr size_t OFF_X2 = OFF_FC  + 65536;
constexpr size_t OFF_P  = OFF_X2  + 16384;
constexpr size_t OFF_C1Q= OFF_P   + 16ull*LMAX;
constexpr size_t OFF_DQ = OFF_C1Q + 3072;
constexpr size_t OFF_C1F= OFF_DQ  + 3072;
constexpr size_t OFF_DF = OFF_C1F + 4096;
constexpr size_t OFF_C1S= OFF_DF  + 4096;
constexpr size_t OFF_DS = OFF_C1S + 512;
constexpr size_t ARENA  = OFF_DS  + 512;

__device__ float G[ARENA];
__device__ int      g_is64;
__device__ unsigned g_cnt;
__device__ unsigned g_gen;

// ---------------- grid barrier ----------------
__device__ __forceinline__ void gsync(unsigned &gen){
    __syncthreads();
    if (threadIdx.x == 0){
        __threadfence();
        if (atomicAdd(&g_cnt, 1u) == gridDim.x - 1u){
            g_cnt = 0u;
            __threadfence();
            *(volatile unsigned*)&g_gen = gen + 1u;
        } else {
            while (*(volatile unsigned*)&g_gen - gen == 0u) __nanosleep(64);
        }
        __threadfence();
    }
    __syncthreads();
    gen++;
}

// ---------------- helpers ----------------
__device__ __forceinline__ float warp_sum(float v){
    #pragma unroll
    for (int o = 16; o; o >>= 1) v += __shfl_down_sync(0xffffffffu, v, o);
    return v;
}
__device__ __forceinline__ float warp_max(float v){
    #pragma unroll
    for (int o = 16; o; o >>= 1) v = fmaxf(v, __shfl_down_sync(0xffffffffu, v, o));
    return v;
}
__device__ __forceinline__ float blk_sum256(float v, float* red){
    int lane = threadIdx.x & 31, w = threadIdx.x >> 5;
    v = warp_sum(v);
    if (lane == 0) red[w] = v;
    __syncthreads();
    if (threadIdx.x < 32){
        float x = (threadIdx.x < 8) ? red[threadIdx.x] : 0.f;
        x = warp_sum(x);
        if (threadIdx.x == 0) red[0] = x;
    }
    __syncthreads();
    float r = red[0];
    __syncthreads();
    return r;
}
__device__ __forceinline__ float blk_max256(float v, float* red){
    int lane = threadIdx.x & 31, w = threadIdx.x >> 5;
    v = warp_max(v);
    if (lane == 0) red[w] = v;
    __syncthreads();
    if (threadIdx.x < 32){
        float x = (threadIdx.x < 8) ? red[threadIdx.x] : -3.4e38f;
        x = warp_max(x);
        if (threadIdx.x == 0) red[0] = x;
    }
    __syncthreads();
    float r = red[0];
    __syncthreads();
    return r;
}
__device__ __forceinline__ float tokf(const int* __restrict__ t, size_t i){
    return g_is64 ? (float)t[i << 1] : (float)t[i];
}
__device__ __forceinline__ float gelu_new_f(float x){
    float u = x + 0.044715f * x * x * x;
    return 0.5f * x * (1.0f + tanhf(GELU_C * u));
}
__device__ __forceinline__ void fma_row(float w, const float4* Xr, float* a){
    #pragma unroll
    for (int i = 0; i < 4; i++){
        float4 x = Xr[i];
        a[4*i+0] = fmaf(w, x.x, a[4*i+0]);
        a[4*i+1] = fmaf(w, x.y, a[4*i+1]);
        a[4*i+2] = fmaf(w, x.z, a[4*i+2]);
        a[4*i+3] = fmaf(w, x.w, a[4*i+3]);
    }
}

// 16-lane batched reduction of per-thread a[16] -> totals in sh[0..15]
__device__ __forceinline__ void red16(const float* a, float* sh){
    __syncthreads();
    #pragma unroll
    for (int b = 0; b < 16; b += 4)
        *(float4*)&sh[threadIdx.x*16 + b] = make_float4(a[b],a[b+1],a[b+2],a[b+3]);
    __syncthreads();
    int b = threadIdx.x & 15, g = threadIdx.x >> 4;
    float v = 0.f;
    #pragma unroll
    for (int j = 0; j < 16; j++) v += sh[(g*16 + j)*16 + b];
    __syncthreads();
    sh[threadIdx.x] = v;
    __syncthreads();
    if (threadIdx.x < 32){
        float t = 0.f;
        if (threadIdx.x < 16)
            #pragma unroll
            for (int g2 = 0; g2 < 16; g2++) t += sh[g2*16 + threadIdx.x];
        __syncwarp();
        if (threadIdx.x < 16) sh[threadIdx.x] = t;
    }
    __syncthreads();
}

// per-batch LN stats of X[1024][16] (single pass; all blocks redundantly)
__device__ __forceinline__ void stats16p(const float* X, float* MU, float* RS, float* sh){
    float s[16], q[16];
    #pragma unroll
    for (int b = 0; b < 16; b++){ s[b] = 0.f; q[b] = 0.f; }
    for (int d = threadIdx.x; d < 1024; d += 256){
        const float4* xr = (const float4*)(X + (size_t)d*16);
        #pragma unroll
        for (int i = 0; i < 4; i++){
            float4 x = xr[i];
            s[4*i+0]+=x.x; q[4*i+0]+=x.x*x.x;
            s[4*i+1]+=x.y; q[4*i+1]+=x.y*x.y;
            s[4*i+2]+=x.z; q[4*i+2]+=x.z*x.z;
            s[4*i+3]+=x.w; q[4*i+3]+=x.w*x.w;
        }
    }
    red16(s, sh);
    if (threadIdx.x < 16) MU[threadIdx.x] = sh[threadIdx.x] * (1.f/1024.f);
    __syncthreads();
    red16(q, sh);
    if (threadIdx.x < 16){
        float mu = MU[threadIdx.x];
        RS[threadIdx.x] = rsqrtf(sh[threadIdx.x]*(1.f/1024.f) - mu*mu + LN_EPS);
    }
    __syncthreads();
}

// batched-16 GEMV tile: r (valid for tid<NC*16) = sum_k X[k][b]*(gam[k]?)*W[k][n0+cc]
template<int NC, bool WT, bool GAM>
__device__ __forceinline__ float gemv_tile(const float* X, const float* __restrict__ W,
    int ldw, int K, int kb, int n0, const float* __restrict__ gam, float* sh){
    constexpr int TPC = 256 / NC;
    const int c = threadIdx.x & (NC-1), sl = threadIdx.x / NC;
    const int n = n0 + c, kper = (K - kb)/TPC, k0 = kb + sl*kper;
    float acc[16];
    #pragma unroll
    for (int b = 0; b < 16; b++) acc[b] = 0.f;
    for (int k = k0; k < k0 + kper; k += 4){
        float w0,w1,w2,w3;
        if (WT){
            float4 w = *(const float4*)&W[(size_t)n*ldw + k];
            w0=w.x; w1=w.y; w2=w.z; w3=w.w;
        } else {
            w0 = W[(size_t)(k+0)*ldw + n];
            w1 = W[(size_t)(k+1)*ldw + n];
            w2 = W[(size_t)(k+2)*ldw + n];
            w3 = W[(size_t)(k+3)*ldw + n];
        }
        if (GAM){ w0*=gam[k]; w1*=gam[k+1]; w2*=gam[k+2]; w3*=gam[k+3]; }
        fma_row(w0, (const float4*)(X + (size_t)(k+0)*16), acc);
        fma_row(w1, (const float4*)(X + (size_t)(k+1)*16), acc);
        fma_row(w2, (const float4*)(X + (size_t)(k+2)*16), acc);
        fma_row(w3, (const float4*)(X + (size_t)(k+3)*16), acc);
    }
    __syncthreads();
    #pragma unroll
    for (int b = 0; b < 16; b += 4)
        *(float4*)&sh[(c*TPC + sl)*16 + b] = make_float4(acc[b],acc[b+1],acc[b+2],acc[b+3]);
    __syncthreads();
    float r = 0.f;
    if (threadIdx.x < NC*16){
        int cc = threadIdx.x >> 4, b2 = threadIdx.x & 15;
        #pragma unroll 4
        for (int j = 0; j < TPC; j++) r += sh[(cc*TPC + j)*16 + b2];
    }
    return r;
}

// ---------------- prep kernels ----------------
__global__ void k_detect(const int* __restrict__ tok){
    __shared__ int cnt;
    if (threadIdx.x == 0) cnt = 0;
    __syncthreads();
    int c = 0;
    for (int i = threadIdx.x; i < 8192; i += 256)
        if (tok[2*i + 1] != 0) c++;
    atomicAdd(&cnt, c);
    __syncthreads();
    if (threadIdx.x == 0) g_is64 = (cnt == 0) ? 1 : 0;
}

__global__ void k_pre_ln(const int* __restrict__ tok,
                         const float* __restrict__ gam, const float* __restrict__ bet){
    __shared__ float red[8];
    int l = blockIdx.x, b = blockIdx.y, tid = threadIdx.x;
    size_t base = ((size_t)b*256 + l)*DD;
    float x[4];
    #pragma unroll
    for (int r = 0; r < 4; r++) x[r] = tokf(tok, base + tid + 256*r);
    float mu = blk_sum256(x[0]+x[1]+x[2]+x[3], red) * (1.f/DD);
    float d0=x[0]-mu, d1=x[1]-mu, d2=x[2]-mu, d3=x[3]-mu;
    float var = blk_sum256(d0*d0+d1*d1+d2*d2+d3*d3, red) * (1.f/DD);
    float rs = rsqrtf(var + LN_EPS);
    size_t o = OFF_H + ((size_t)b*255 + l)*DD;
    G[o+tid    ] = d0*rs*gam[tid    ] + bet[tid    ];
    G[o+tid+256] = d1*rs*gam[tid+256] + bet[tid+256];
    G[o+tid+512] = d2*rs*gam[tid+512] + bet[tid+512];
    G[o+tid+768] = d3*rs*gam[tid+768] + bet[tid+768];
}

__global__ void __launch_bounds__(256) k_pre_gemm(const float* __restrict__ Wq,
                                                  const float* __restrict__ bqkv){
    __shared__ float As[16][128];
    __shared__ float Bs[16][128];
    const int M = 16*255;
    int tid = threadIdx.x;
    int n0 = blockIdx.x*128, m0 = blockIdx.y*128;
    int tx = tid & 15, ty = tid >> 4;
    float acc[8][8];
    #pragma unroll
    for (int i = 0; i < 8; i++)
        #pragma unroll
        for (int j = 0; j < 8; j++) acc[i][j] = 0.f;
    int ar = tid >> 2, ak = (tid & 3)*4;
    int bk = tid >> 4, bn = (tid & 15)*4;
    for (int k0 = 0; k0 < 1024; k0 += 16){
        #pragma unroll
        for (int rr = 0; rr < 2; rr++){
            int m = m0 + ar + rr*64;
            float4 a = (m < M) ? *(const float4*)&G[OFF_H + (size_t)m*DD + k0 + ak]
                               : make_float4(0.f,0.f,0.f,0.f);
            As[ak+0][ar+rr*64]=a.x; As[ak+1][ar+rr*64]=a.y;
            As[ak+2][ar+rr*64]=a.z; As[ak+3][ar+rr*64]=a.w;
            float4 bv = *(const float4*)&Wq[(size_t)(k0+bk)*3072 + 1024 + n0 + bn + rr*64];
            *(float4*)&Bs[bk][bn+rr*64] = bv;
        }
        __syncthreads();
        #pragma unroll
        for (int kk = 0; kk < 16; kk++){
            float ra[8], rb[8];
            *(float4*)&ra[0]=*(float4*)&As[kk][ty*8]; *(float4*)&ra[4]=*(float4*)&As[kk][ty*8+4];
            *(float4*)&rb[0]=*(float4*)&Bs[kk][tx*8]; *(float4*)&rb[4]=*(float4*)&Bs[kk][tx*8+4];
            #pragma unroll
            for (int i = 0; i < 8; i++)
                #pragma unroll
                for (int j = 0; j < 8; j++) acc[i][j] = fmaf(ra[i], rb[j], acc[i][j]);
        }
        __syncthreads();
    }
    #pragma unroll
    for (int i = 0; i < 8; i++){
        int m = m0 + ty*8 + i;
        if (m >= M) continue;
        int bidx = m/255, l = m%255;
        size_t co = ((size_t)bidx*LMAX + l)*DD;
        #pragma unroll
        for (int j = 0; j < 8; j += 4){
            int n = n0 + tx*8 + j;
            float4 v;
            v.x = acc[i][j+0] + bqkv[1024+n+0];
            v.y = acc[i][j+1] + bqkv[1024+n+1];
            v.z = acc[i][j+2] + bqkv[1024+n+2];
            v.w = acc[i][j+3] + bqkv[1024+n+3];
            if (n < 1024) *(float4*)&G[OFF_K + co + n]        = v;
            else          *(float4*)&G[OFF_V + co + n - 1024] = v;
        }
    }
}

__global__ void k_set_e0(const int* __restrict__ tok){
    int b = blockIdx.x, tid = threadIdx.x;
    size_t base = ((size_t)b*256 + 255)*DD;
    #pragma unroll
    for (int r = 0; r < 4; r++){
        int d = tid + 256*r;
        G[OFF_E + (size_t)d*16 + b] = tokf(tok, base + d);
    }
}

// column sums: c1[n]=sum gam[k]W[k][n]; dd[n]=sum bet[k]W[k][n]+bias[n]
__global__ void k_fold(const float* __restrict__ W, const float* __restrict__ gam,
                       const float* __restrict__ bet, const float* __restrict__ bias,
                       size_t c1off, size_t ddoff, int K, int N){
    __shared__ float a1[256], a2[256];
    int n = blockIdx.x*64 + (threadIdx.x & 63);
    int seg = threadIdx.x >> 6;
    float s1 = 0.f, s2 = 0.f;
    for (int k = seg; k < K; k += 4){
        float w = W[(size_t)k*N + n];
        s1 = fmaf(gam[k], w, s1);
        s2 = fmaf(bet[k], w, s2);
    }
    a1[threadIdx.x] = s1; a2[threadIdx.x] = s2;
    __syncthreads();
    if (seg == 0){
        int i = threadIdx.x;
        G[c1off + n] = a1[i] + a1[i+64] + a1[i+128] + a1[i+192];
        G[ddoff + n] = a2[i] + a2[i+64] + a2[i+128] + a2[i+192] + (bias ? bias[n] : 0.f);
    }
}

// row-major W[512][1024] variant (score head, no bias)
__global__ void k_folds(const float* __restrict__ W, const float* __restrict__ gam,
                        const float* __restrict__ bet, size_t c1off, size_t ddoff){
    __shared__ float red[8];
    int n = blockIdx.x;
    float s1 = 0.f, s2 = 0.f;
    for (int k = threadIdx.x; k < 1024; k += 256){
        float w = W[(size_t)n*1024 + k];
        s1 = fmaf(gam[k], w, s1);
        s2 = fmaf(bet[k], w, s2);
    }
    s1 = blk_sum256(s1, red);
    s2 = blk_sum256(s2, red);
    if (threadIdx.x == 0){ G[c1off + n] = s1; G[ddoff + n] = s2; }
}

// ---------------- persistent decode kernel ----------------
__global__ void __launch_bounds__(256, 1)
k_decode(const float* __restrict__ Wqkv, const float* __restrict__ g1,
         const float* __restrict__ Wap,  const float* __restrict__ bap,
         const float* __restrict__ g2,   const float* __restrict__ Wfc,
         const float* __restrict__ Wmp,  const float* __restrict__ bmp,
         const float* __restrict__ gf,   const float* __restrict__ Wsc,
         float* __restrict__ out){
    __shared__ float sh[4096];
    __shared__ float MU[16], RS[16], red[8];
    unsigned gen = *(volatile unsigned*)&g_gen;
    const int bid = blockIdx.x, tid = threadIdx.x;

    for (int t = 0; t < 32; t++){
        const int pos = 255 + t, L = 256 + t;
        const int kb = (t == 0) ? 0 : 512;   // E lower half exactly zero for t>=1

        // 1) stats(E) + qkv GEMV (LN1-folded)
        stats16p(&G[OFF_E], MU, RS, sh);
        for (int tile = bid; tile < 192; tile += NBLK){
            float r = gemv_tile<16,false,true>(&G[OFF_E], Wqkv, 3072, 1024, kb, tile*16, g1, sh);
            int cc = tid >> 4, b = tid & 15, nn = tile*16 + cc;
            float v = RS[b]*(r - MU[b]*G[OFF_C1Q + nn]) + G[OFF_DQ + nn];
            if (nn < 1024)      G[OFF_Q + (size_t)nn*16 + b] = v;
            else if (nn < 2048) G[OFF_K + ((size_t)b*LMAX + pos)*DD + nn - 1024] = v;
            else                G[OFF_V + ((size_t)b*LMAX + pos)*DD + nn - 2048] = v;
        }
        gsync(gen);

        // 2) scores (blocks 0..127: 8 per batch)
        if (bid < 128){
            int b = bid >> 3, part = bid & 7;
            for (int d = tid; d < 1024; d += 256) sh[d] = G[OFF_Q + (size_t)d*16 + b];
            __syncthreads();
            int warp = tid >> 5, lane = tid & 31;
            for (int l = part + 8*warp; l < L; l += 64){
                const float* kc = &G[OFF_K + ((size_t)b*LMAX + l)*DD];
                float a = 0.f;
                #pragma unroll
                for (int i = 0; i < 8; i++){
                    int d = lane*4 + i*128;
                    float4 kv = *(const float4*)&kc[d];
                    float4 qv = *(const float4*)&sh[d];
                    a = fmaf(kv.x,qv.x,a); a = fmaf(kv.y,qv.y,a);
                    a = fmaf(kv.z,qv.z,a); a = fmaf(kv.w,qv.w,a);
                }
                a = warp_sum(a);
                if (lane == 0) G[OFF_P + (size_t)b*LMAX + l] = a * 0.03125f;
            }
        }
        gsync(gen);

        // 3) softmax (redundant x8) + P@V (d-split x8)
        if (bid < 128){
            int b = bid >> 3, part = bid & 7;
            float m = -3.4e38f;
            for (int l = tid; l < L; l += 256) m = fmaxf(m, G[OFF_P + (size_t)b*LMAX + l]);
            m = blk_max256(m, red);
            float e = 0.f;
            for (int l = tid; l < L; l += 256){
                float ev = expf(G[OFF_P + (size_t)b*LMAX + l] - m);
                sh[l] = ev; e += ev;
            }
            float iz = 1.f / blk_sum256(e, red);
            if (tid < 128){
                int d = part*128 + tid;
                const float* vc = &G[OFF_V + (size_t)b*LMAX*DD + d];
                float a0=0.f,a1=0.f,a2=0.f,a3=0.f;
                int l = 0;
                for (; l + 4 <= L; l += 4){
                    a0 = fmaf(sh[l+0], vc[(size_t)(l+0)*DD], a0);
                    a1 = fmaf(sh[l+1], vc[(size_t)(l+1)*DD], a1);
                    a2 = fmaf(sh[l+2], vc[(size_t)(l+2)*DD], a2);
                    a3 = fmaf(sh[l+3], vc[(size_t)(l+3)*DD], a3);
                }
                for (; l < L; l++) a0 = fmaf(sh[l], vc[(size_t)l*DD], a0);
                G[OFF_ATT + (size_t)d*16 + b] = ((a0+a1)+(a2+a3)) * iz;
            }
        }
        gsync(gen);

        // 4) x1 = E + ATT@Wap + bap
        for (int tile = bid; tile < 128; tile += NBLK){
            float r = gemv_tile<8,false,false>(&G[OFF_ATT], Wap, 1024, 1024, 0, tile*8, g1, sh);
            if (tid < 128){
                int cc = tid >> 4, b = tid & 15, nn = tile*8 + cc;
                G[OFF_X1 + (size_t)nn*16 + b] = G[OFF_E + (size_t)nn*16 + b] + r + bap[nn];
            }
        }
        gsync(gen);

        // 5) stats(x1) + fc GEMV (LN2-folded) + gelu
        stats16p(&G[OFF_X1], MU, RS, sh);
        for (int tile = bid; tile < 256; tile += NBLK){
            float r = gemv_tile<16,false,true>(&G[OFF_X1], Wfc, 4096, 1024, 0, tile*16, g2, sh);
            int cc = tid >> 4, b = tid & 15, nn = tile*16 + cc;
            float v = RS[b]*(r - MU[b]*G[OFF_C1F + nn]) + G[OFF_DF + nn];
            G[OFF_FC + (size_t)nn*16 + b] = gelu_new_f(v);
        }
        gsync(gen);

        // 6) x2 = x1 + FC@Wmp + bmp
        for (int tile = bid; tile < 128; tile += NBLK){
            float r = gemv_tile<8,false,false>(&G[OFF_FC], Wmp, 1024, 4096, 0, tile*8, g1, sh);
            if (tid < 128){
                int cc = tid >> 4, b = tid & 15, nn = tile*8 + cc;
                G[OFF_X2 + (size_t)nn*16 + b] = G[OFF_X1 + (size_t)nn*16 + b] + r + bmp[nn];
            }
        }
        gsync(gen);

        // 7) stats(x2) + score head (LNf-folded) -> logits + next E
        stats16p(&G[OFF_X2], MU, RS, sh);
        for (int tile = bid; tile < 128; tile += NBLK){
            float r = gemv_tile<4,true,true>(&G[OFF_X2], Wsc, 1024, 1024, 0, tile*4, gf, sh);
            if (tid < 64){
                int cc = tid >> 4, b = tid & 15, nn = tile*4 + cc;
                float lg = RS[b]*(r - MU[b]*G[OFF_C1S + nn]) + G[OFF_DS + nn];
                out[(size_t)b*16384 + (size_t)t*512 + nn] = lg;
                G[OFF_E + (size_t)(512 + nn)*16 + b] = (lg > 0.f) ? 1.f : 0.f;
                G[OFF_E + (size_t)nn*16 + b] = 0.f;
            }
        }
        gsync(gen);
    }
}

// ---------------- host ----------------
extern "C" void kernel_launch(void* const* d_in, const int* in_sizes, int n_in,
                              void* d_out, int out_size){
    const int*   tok     = (const int*)  d_in[0];
    const float* W_qkv   = (const float*)d_in[1];
    const float* b_qkv   = (const float*)d_in[2];
    const float* W_aproj = (const float*)d_in[3];
    const float* b_aproj = (const float*)d_in[4];
    const float* g_ln1   = (const float*)d_in[5];
    const float* b_ln1   = (const float*)d_in[6];
    const float* g_ln2   = (const float*)d_in[7];
    const float* b_ln2   = (const float*)d_in[8];
    const float* W_fc    = (const float*)d_in[9];
    const float* b_fc    = (const float*)d_in[10];
    const float* W_mproj = (const float*)d_in[11];
    const float* b_mproj = (const float*)d_in[12];
    const float* g_lnf   = (const float*)d_in[13];
    const float* b_lnf   = (const float*)d_in[14];
    const float* W_score = (const float*)d_in[15];
    float* out = (float*)d_out;

    k_detect<<<1, 256>>>(tok);
    k_pre_ln<<<dim3(255, 16), 256>>>(tok, g_ln1, b_ln1);
    k_pre_gemm<<<dim3(16, 32), 256>>>(W_qkv, b_qkv);
    k_set_e0<<<16, 256>>>(tok);
    k_fold<<<48, 256>>>(W_qkv, g_ln1, b_ln1, b_qkv, OFF_C1Q, OFF_DQ, 1024, 3072);
    k_fold<<<64, 256>>>(W_fc,  g_ln2, b_ln2, b_fc,  OFF_C1F, OFF_DF, 1024, 4096);
    k_folds<<<512, 256>>>(W_score, g_lnf, b_lnf, OFF_C1S, OFF_DS);
    k_decode<<<NBLK, 256>>>(W_qkv, g_ln1, W_aproj, b_aproj, g_ln2, W_fc,
                            W_mproj, b_mproj, g_lnf, W_score, out);
}